// round 3
// baseline (speedup 1.0000x reference)
#include <cuda_runtime.h>
#include <cstdint>

#define N2    361
#define NTHR  384
#define NBITS 32768
#define NWORDS (NBITS / 32)
#define GMAX  64
#define NEGV  (-1000000000.0f)
#define I32MIN_V (-2147483647 - 1)

__global__ __launch_bounds__(NTHR, 4)
void go_mask_kernel(const float* __restrict__ logits,
                    const int* __restrict__ legal,      // bool serialized as int32 (0/1)
                    const int* __restrict__ player,
                    const int* __restrict__ cur_hash,
                    const int* __restrict__ hist,
                    const int* __restrict__ move_count,
                    const int* __restrict__ ZposT,
                    const int* __restrict__ sgi,
                    const int* __restrict__ sp,
                    const int* __restrict__ gp,
                    const int* __restrict__ cap,
                    float* __restrict__ out)
{
    __shared__ int      sh_z[3 * N2];     // Zobrist rows: empty, black, white
    __shared__ int      sh_hist[N2];      // this board's history
    __shared__ unsigned sh_bits[NWORDS];  // bloom bitset
    __shared__ int      sh_gx[GMAX];      // per-local-group XOR

    const int b = blockIdx.x;
    const int t = threadIdx.x;

    // --- cooperative loads ---
    for (int i = t; i < 3 * N2; i += NTHR) sh_z[i] = ZposT[i];
    for (int i = t; i < NWORDS; i += NTHR) sh_bits[i] = 0u;

    int mc = move_count[b];
    if (mc < 0)  mc = 0;
    if (mc > N2) mc = N2;

    if (t < N2) sh_hist[t] = hist[(size_t)b * N2 + t];

    const int pl = player[b];
    const int ch = cur_hash[b];
    const int g0 = gp[b];
    int nG = gp[b + 1] - g0;
    if (nG > GMAX) nG = GMAX;
    if (nG < 0)    nG = 0;

    __syncthreads();

    // --- per-group XOR of (z_opp ^ z_empty) over the group's stones ---
    if (t < nG) {
        const int gg = g0 + t;
        const int s0 = sp[gg];
        const int s1 = sp[gg + 1];
        const int opp_row = (2 - pl) * N2;   // row index 1 + (1 - pl)
        int acc = 0;
        for (int s = s0; s < s1; ++s) {
            int si = sgi[s];
            si = si < 0 ? 0 : (si >= N2 ? N2 - 1 : si);
            acc ^= sh_z[opp_row + si] ^ sh_z[si];
        }
        sh_gx[t] = acc;
    }

    // --- bloom insert: valid history entries + I32MIN sentinel if mc < M ---
    if (t < N2) {
        int  key = 0;
        bool ins = false;
        if (t < mc)        { key = sh_hist[t]; ins = true; }
        else if (t == mc)  { key = I32MIN_V;   ins = true; }  // t<N2 => mc<N2
        if (ins) {
            const unsigned h  = (unsigned)key * 2654435761u;
            const unsigned b1 = h & (NBITS - 1);
            const unsigned b2 = (h >> 15) & (NBITS - 1);
            atomicOr(&sh_bits[b1 >> 5], 1u << (b1 & 31));
            atomicOr(&sh_bits[b2 >> 5], 1u << (b2 & 31));
        }
    }
    __syncthreads();

    // --- per-position candidate hash + membership + output ---
    if (t < N2) {
        const size_t idx = (size_t)b * N2 + t;

        // capture delta: coalesced 16B load
        const int4 c4 = *reinterpret_cast<const int4*>(cap + idx * 4);
        int cd = 0;
        {
            int c;
            c = c4.x; if (c >= 0) { int l = c >= GMAX ? GMAX - 1 : c; cd ^= sh_gx[l]; }
            c = c4.y; if (c >= 0) { int l = c >= GMAX ? GMAX - 1 : c; cd ^= sh_gx[l]; }
            c = c4.z; if (c >= 0) { int l = c >= GMAX ? GMAX - 1 : c; cd ^= sh_gx[l]; }
            c = c4.w; if (c >= 0) { int l = c >= GMAX ? GMAX - 1 : c; cd ^= sh_gx[l]; }
        }

        // placement delta
        const int mrow = (pl == 0 ? 1 : 2) * N2;
        const int pd   = sh_z[t] ^ sh_z[mrow + t];

        const int cand = ch ^ pd ^ cd;

        // bloom check (2 probes)
        const unsigned h  = (unsigned)cand * 2654435761u;
        const unsigned b1 = h & (NBITS - 1);
        const unsigned b2 = (h >> 15) & (NBITS - 1);
        const bool maybe = (((sh_bits[b1 >> 5] >> (b1 & 31)) &
                             (sh_bits[b2 >> 5] >> (b2 & 31))) & 1u) != 0u;

        bool rep = false;
        if (maybe) {
            if (mc < N2 && cand == I32MIN_V) {
                rep = true;                       // sentinel in the masked set
            } else {
                for (int j = 0; j < mc; ++j) {
                    if (sh_hist[j] == cand) { rep = true; break; }
                }
            }
        }

        const float lg = logits[idx];
        const bool  ok = (legal[idx] != 0) && !rep;
        out[idx] = ok ? lg : NEGV;
    }
}

extern "C" void kernel_launch(void* const* d_in, const int* in_sizes, int n_in,
                              void* d_out, int out_size)
{
    const float* logits = (const float*)d_in[0];
    const int*   legal  = (const int*)d_in[1];
    const int*   player = (const int*)d_in[2];
    const int*   chash  = (const int*)d_in[3];
    const int*   hist   = (const int*)d_in[4];
    const int*   mcnt   = (const int*)d_in[5];
    const int*   zpos   = (const int*)d_in[6];
    const int*   sgi    = (const int*)d_in[7];
    const int*   sp     = (const int*)d_in[8];
    const int*   gp     = (const int*)d_in[9];
    const int*   cap    = (const int*)d_in[10];
    float*       out    = (float*)d_out;

    const int B = in_sizes[2];  // current_player has B elements

    go_mask_kernel<<<B, NTHR>>>(logits, legal, player, chash, hist, mcnt,
                                zpos, sgi, sp, gp, cap, out);
}